// round 15
// baseline (speedup 1.0000x reference)
#include <cuda_runtime.h>
#include <cuda_bf16.h>
#include <math.h>

// QuantumLayer as a multilinear polynomial (exact identity):
//   out_o(x) = T[o] . (1,cos x0,sin x0) x ... x (1,cos x3,sin x3)
// T (4 x 3^4) built by sampling the circuit at {0,pi/2,pi}^4 + inverse 3x3
// Vandermonde. Two kernels under PDL (champion structure).
// R15: hot kernel switched to grid=1184, 1 element/iteration with a scalar-only
// loop + register prefetch. Removes the 13.5% wave-quantization penalty
// (2048 equal blocks over 592 slots -> 3.46 waves) identified from R3/R4:
// 18.6us FFMA floor x 1.135 = 21.2 matched both measurements exactly.

__device__ __align__(16) float g_T[432];  // [o][k0][k1][k2][k3 padded to 4]

#define SHFL8(v, m) __shfl_xor_sync(0xFFFFFFFFu, (v), (m), 8)

// ---------------------------------------------------------------------------
// Kernel 1: build T. One block, 672 threads = 21 warps x 4 samples x 8 lanes.
// ---------------------------------------------------------------------------
__global__ void build_T_kernel(const float* __restrict__ w) {
    // Let the PDL secondary launch immediately; everything it does before
    // cudaGridDependencySynchronize() is T-independent.
    cudaTriggerProgrammaticLaunchCompletion();

    __shared__ float bufA[324], bufB[324];
    __shared__ float wc[12], wsn[12];
    const int t = threadIdx.x;

    if (t < 12) {
        float s, c;
        __sincosf(0.5f * w[t], &s, &c);
        wc[t] = c; wsn[t] = s;
    }
    __syncthreads();

    const int lane = t & 31;
    const int s    = lane & 7;                    // slot: owns amps s and s+8
    const int sm   = (t >> 5) * 4 + (lane >> 3);  // sample id (0..83; >=81 unused)

    const int a0 = sm / 27, a1 = (sm / 9) % 3, a2 = (sm / 3) % 3, a3 = sm % 3;
    const float R = 0.70710678118654752f;
    const float hc0 = (a0 == 0) ? 1.f : (a0 == 1) ? R : 0.f;
    const float hs0 = (a0 == 0) ? 0.f : (a0 == 1) ? R : 1.f;
    const float hc1 = (a1 == 0) ? 1.f : (a1 == 1) ? R : 0.f;
    const float hs1 = (a1 == 0) ? 0.f : (a1 == 1) ? R : 1.f;
    const float hc2 = (a2 == 0) ? 1.f : (a2 == 1) ? R : 0.f;
    const float hs2 = (a2 == 0) ? 0.f : (a2 == 1) ? R : 1.f;
    const float hc3 = (a3 == 0) ? 1.f : (a3 == 1) ? R : 0.f;
    const float hs3 = (a3 == 0) ? 0.f : (a3 == 1) ? R : 1.f;

    // Post-input-RX product state: amp_j = (-i)^popc(j) * prod_q f_q(bit(3-q))
    const float f1 = ((s >> 2) & 1) ? hs1 : hc1;
    const float f2 = ((s >> 1) & 1) ? hs2 : hc2;
    const float f3 = (s & 1)        ? hs3 : hc3;
    const float rest = f1 * f2 * f3;
    const float m0 = hc0 * rest;   // amp j=s   (bit3=0)
    const float m1 = hs0 * rest;   // amp j=s+8 (bit3=1)

    const int pc0 = __popc(s) & 3;
    const int pc1 = (pc0 + 1) & 3;
    float ar0 = (pc0 == 0) ?  m0 : (pc0 == 2) ? -m0 : 0.f;
    float ai0 = (pc0 == 1) ? -m0 : (pc0 == 3) ?  m0 : 0.f;
    float ar1 = (pc1 == 0) ?  m1 : (pc1 == 2) ? -m1 : 0.f;
    float ai1 = (pc1 == 1) ? -m1 : (pc1 == 3) ?  m1 : 0.f;

#pragma unroll
    for (int l = 0; l < 3; l++) {
        {   // RX on qubit0 (bit8): partner is own other amp.
            const float cq = wc[l * 4 + 0], sq = wsn[l * 4 + 0];
            float nr0 = fmaf(cq, ar0,  sq * ai1);
            float ni0 = fmaf(cq, ai0, -sq * ar1);
            float nr1 = fmaf(cq, ar1,  sq * ai0);
            float ni1 = fmaf(cq, ai1, -sq * ar0);
            ar0 = nr0; ai0 = ni0; ar1 = nr1; ai1 = ni1;
        }
#pragma unroll
        for (int q = 1; q < 4; q++) {  // bits 4,2,1 -> partner slot s^b
            const int b = 8 >> q;
            const float cq = wc[l * 4 + q], sq = wsn[l * 4 + q];
            float pr0 = SHFL8(ar0, b), pi0 = SHFL8(ai0, b);
            float pr1 = SHFL8(ar1, b), pi1 = SHFL8(ai1, b);
            float nr0 = fmaf(cq, ar0,  sq * pi0);
            float ni0 = fmaf(cq, ai0, -sq * pr0);
            float nr1 = fmaf(cq, ar1,  sq * pi1);
            float ni1 = fmaf(cq, ai1, -sq * pr1);
            ar0 = nr0; ai0 = ni0; ar1 = nr1; ai1 = ni1;
        }
        // CNOT(0,1): ctrl bit3, tgt bit4 — amp1 <- slot s^4's amp1.
        {
            float tr = SHFL8(ar1, 4), ti = SHFL8(ai1, 4);
            ar1 = tr; ai1 = ti;
        }
        // CNOT(1,2): ctrl bit2 (of s), tgt bit2.
        {
            float pr0 = SHFL8(ar0, 2), pi0 = SHFL8(ai0, 2);
            float pr1 = SHFL8(ar1, 2), pi1 = SHFL8(ai1, 2);
            const bool ct = (s >> 2) & 1;
            ar0 = ct ? pr0 : ar0;  ai0 = ct ? pi0 : ai0;
            ar1 = ct ? pr1 : ar1;  ai1 = ct ? pi1 : ai1;
        }
        // CNOT(2,3): ctrl bit1 (of s), tgt bit1.
        {
            float pr0 = SHFL8(ar0, 1), pi0 = SHFL8(ai0, 1);
            float pr1 = SHFL8(ar1, 1), pi1 = SHFL8(ai1, 1);
            const bool ct = (s >> 1) & 1;
            ar0 = ct ? pr0 : ar0;  ai0 = ct ? pi0 : ai0;
            ar1 = ct ? pr1 : ar1;  ai1 = ct ? pi1 : ai1;
        }
        // CNOT(3,0): ctrl bit0 (of s), tgt bit8 — in-thread amp swap.
        {
            const bool ct = s & 1;
            float tr = ar0, ti = ai0;
            ar0 = ct ? ar1 : ar0;  ai0 = ct ? ai1 : ai0;
            ar1 = ct ? tr  : ar1;  ai1 = ct ? ti  : ai1;
        }
    }

    // Probabilities + 4 signed (Walsh) sums reduced over the 8 slots.
    const float p0 = ar0 * ar0 + ai0 * ai0;
    const float p1 = ar1 * ar1 + ai1 * ai1;
    const float tsum = p0 + p1, tdiff = p0 - p1;
    float v0 = tdiff;
    float v1 = ((s >> 2) & 1) ? -tsum : tsum;
    float v2 = ((s >> 1) & 1) ? -tsum : tsum;
    float v3 = (s & 1)        ? -tsum : tsum;
#pragma unroll
    for (int d = 1; d < 8; d <<= 1) {
        v0 += SHFL8(v0, d);
        v1 += SHFL8(v1, d);
        v2 += SHFL8(v2, d);
        v3 += SHFL8(v3, d);
    }
    if (s == 0 && sm < 81) {
        bufA[0 * 81 + sm] = v0;
        bufA[1 * 81 + sm] = v1;
        bufA[2 * 81 + sm] = v2;
        bufA[3 * 81 + sm] = v3;
    }
    __syncthreads();

    // Inverse Vandermonde per axis (samples {0,pi/2,pi}, basis (1,cos,sin)):
    //   c0 = (s0+s2)/2 ; c1 = (s0-s2)/2 ; c2 = s1 - (s0+s2)/2
    const float Vi[3][3] = {{0.5f, 0.0f, 0.5f},
                            {0.5f, 0.0f, -0.5f},
                            {-0.5f, 1.0f, -0.5f}};
    const int WST[4] = {27, 9, 3, 1};
    float* src = bufA;
    float* dst = bufB;
    for (int ax = 3; ax >= 0; ax--) {
        if (t < 324) {
            const int o = t / 81, e = t % 81;
            const int ws2 = WST[ax];
            const int k = (e / ws2) % 3;
            const int eb = e - k * ws2;
            const float* sp = src + o * 81;
            dst[t] = Vi[k][0] * sp[eb] + Vi[k][1] * sp[eb + ws2] + Vi[k][2] * sp[eb + 2 * ws2];
        }
        __syncthreads();
        float* tmp = src; src = dst; dst = tmp;
    }

    if (t < 432) {
        const int o = t / 108, r = t % 108, k012 = r / 4, c = r % 4;
        g_T[t] = (c < 3) ? src[o * 81 + k012 * 3 + c] : 0.0f;
    }
}

// ---------------------------------------------------------------------------
// Kernel 2: grid-strided 1-element loop, scalar-only state, PDL-gated T read.
// 320 FMA/element Horner over T.
// ---------------------------------------------------------------------------
#define HOT_GRID 1184   // 148 SMs x 4 blocks x 2 waves

__global__ __launch_bounds__(256, 4) void qlayer_kernel(
    const float* __restrict__ x, float* __restrict__ out, int B)
{
    __shared__ __align__(16) float4 shT[108];   // [o*27 + k0*9 + k1*3 + k2], .xyz = k3
    const int t   = threadIdx.x;
    const int gid = blockIdx.x * 256 + t;
    const int stride = gridDim.x * 256;

    const float4* __restrict__ x4 = (const float4*)x;
    float4* __restrict__ o4 = (float4*)out;

    // Prefetch first element (T-independent; overlaps build_T under PDL).
    float4 v = make_float4(0.f, 0.f, 0.f, 0.f);
    if (gid < B) v = x4[gid];

    // Gate: wait for build_T completion + memory visibility.
    cudaGridDependencySynchronize();

    if (t < 108) shT[t] = __ldcg(((const float4*)g_T) + t);
    __syncthreads();

    for (int e = gid; e < B; e += stride) {
        // Prefetch next element into registers (hides LDG latency).
        const int en = e + stride;
        const float4 vn = x4[(en < B) ? en : e];

        float c0, s0, c1, s1, c2, s2, c3, s3;
        __sincosf(v.x, &s0, &c0);
        __sincosf(v.y, &s1, &c1);
        __sincosf(v.z, &s2, &c2);
        __sincosf(v.w, &s3, &c3);

        float o0, o1, o2, o3;
#pragma unroll
        for (int o = 0; o < 4; o++) {
            float acc;
#pragma unroll
            for (int k0 = 0; k0 < 3; k0++) {
                float Aacc;
#pragma unroll
                for (int k1 = 0; k1 < 3; k1++) {
                    float Bacc;
#pragma unroll
                    for (int k2 = 0; k2 < 3; k2++) {
                        const float4 tq = shT[o * 27 + k0 * 9 + k1 * 3 + k2];
                        const float D = fmaf(tq.z, s3, fmaf(tq.y, c3, tq.x));
                        if (k2 == 0)      Bacc = D;
                        else if (k2 == 1) Bacc = fmaf(c2, D, Bacc);
                        else              Bacc = fmaf(s2, D, Bacc);
                    }
                    if (k1 == 0)      Aacc = Bacc;
                    else if (k1 == 1) Aacc = fmaf(c1, Bacc, Aacc);
                    else              Aacc = fmaf(s1, Bacc, Aacc);
                }
                if (k0 == 0)      acc = Aacc;
                else if (k0 == 1) acc = fmaf(c0, Aacc, acc);
                else              acc = fmaf(s0, Aacc, acc);
            }
            if (o == 0)      o0 = acc;
            else if (o == 1) o1 = acc;
            else if (o == 2) o2 = acc;
            else             o3 = acc;
        }

        o4[e] = make_float4(o0, o1, o2, o3);
        v = vn;
    }
}

// ---------------------------------------------------------------------------
extern "C" void kernel_launch(void* const* d_in, const int* in_sizes, int n_in,
                              void* d_out, int out_size) {
    const float* xp = (const float*)d_in[0];
    const float* wp = (const float*)d_in[1];
    int sx = in_sizes[0];
    if (n_in >= 2 && in_sizes[0] == 12 && in_sizes[1] != 12) {
        xp = (const float*)d_in[1];
        wp = (const float*)d_in[0];
        sx = in_sizes[1];
    }
    const int B = sx / 4;

    build_T_kernel<<<1, 672>>>(wp);

    int grid = HOT_GRID;
    const int maxg = (B + 255) / 256;
    if (grid > maxg) grid = maxg;

    // PDL: secondary may launch as soon as build_T triggers (at its start);
    // the in-kernel cudaGridDependencySynchronize() gates the T read.
    cudaLaunchConfig_t cfg = {};
    cfg.gridDim = dim3((unsigned)grid);
    cfg.blockDim = dim3(256);
    cfg.dynamicSmemBytes = 0;
    cfg.stream = 0;
    cudaLaunchAttribute attr[1];
    attr[0].id = cudaLaunchAttributeProgrammaticStreamSerialization;
    attr[0].val.programmaticStreamSerializationAllowed = 1;
    cfg.attrs = attr;
    cfg.numAttrs = 1;
    cudaError_t err = cudaLaunchKernelEx(&cfg, qlayer_kernel, xp, (float*)d_out, B);
    if (err != cudaSuccess) {
        qlayer_kernel<<<grid, 256>>>(xp, (float*)d_out, B);
    }
}

// round 16
// speedup vs baseline: 3.4726x; 3.4726x over previous
#include <cuda_runtime.h>
#include <cuda_bf16.h>
#include <math.h>

// QuantumLayer as a multilinear polynomial (exact identity):
//   out_o(x) = T[o] . (1,cos x0,sin x0) x ... x (1,cos x3,sin x3)
// T (4 x 3^4) built by sampling the circuit at {0,pi/2,pi}^4 + inverse 3x3
// Vandermonde. Two kernels under PDL (champion structure).
// R16: hot kernel E=1 (ONE element/thread, straight-line, NO loop) with
// grid=4096: 6.92 waves over 592 slots -> 1.2% wave-quantization idle vs
// 13.5% at E=2/grid=2048. Loop-free because every looped form (grid-stride
// R11/R12/R15) triggers ptxas local-memory demotion (35x DRAM traffic).

__device__ __align__(16) float g_T[432];  // [o][k0][k1][k2][k3 padded to 4]

#define SHFL8(v, m) __shfl_xor_sync(0xFFFFFFFFu, (v), (m), 8)

// ---------------------------------------------------------------------------
// Kernel 1: build T. One block, 672 threads = 21 warps x 4 samples x 8 lanes.
// ---------------------------------------------------------------------------
__global__ void build_T_kernel(const float* __restrict__ w) {
    // Let the PDL secondary launch immediately; everything it does before
    // cudaGridDependencySynchronize() is T-independent.
    cudaTriggerProgrammaticLaunchCompletion();

    __shared__ float bufA[324], bufB[324];
    __shared__ float wc[12], wsn[12];
    const int t = threadIdx.x;

    if (t < 12) {
        float s, c;
        __sincosf(0.5f * w[t], &s, &c);
        wc[t] = c; wsn[t] = s;
    }
    __syncthreads();

    const int lane = t & 31;
    const int s    = lane & 7;                    // slot: owns amps s and s+8
    const int sm   = (t >> 5) * 4 + (lane >> 3);  // sample id (0..83; >=81 unused)

    const int a0 = sm / 27, a1 = (sm / 9) % 3, a2 = (sm / 3) % 3, a3 = sm % 3;
    const float R = 0.70710678118654752f;
    const float hc0 = (a0 == 0) ? 1.f : (a0 == 1) ? R : 0.f;
    const float hs0 = (a0 == 0) ? 0.f : (a0 == 1) ? R : 1.f;
    const float hc1 = (a1 == 0) ? 1.f : (a1 == 1) ? R : 0.f;
    const float hs1 = (a1 == 0) ? 0.f : (a1 == 1) ? R : 1.f;
    const float hc2 = (a2 == 0) ? 1.f : (a2 == 1) ? R : 0.f;
    const float hs2 = (a2 == 0) ? 0.f : (a2 == 1) ? R : 1.f;
    const float hc3 = (a3 == 0) ? 1.f : (a3 == 1) ? R : 0.f;
    const float hs3 = (a3 == 0) ? 0.f : (a3 == 1) ? R : 1.f;

    // Post-input-RX product state: amp_j = (-i)^popc(j) * prod_q f_q(bit(3-q))
    const float f1 = ((s >> 2) & 1) ? hs1 : hc1;
    const float f2 = ((s >> 1) & 1) ? hs2 : hc2;
    const float f3 = (s & 1)        ? hs3 : hc3;
    const float rest = f1 * f2 * f3;
    const float m0 = hc0 * rest;   // amp j=s   (bit3=0)
    const float m1 = hs0 * rest;   // amp j=s+8 (bit3=1)

    const int pc0 = __popc(s) & 3;
    const int pc1 = (pc0 + 1) & 3;
    float ar0 = (pc0 == 0) ?  m0 : (pc0 == 2) ? -m0 : 0.f;
    float ai0 = (pc0 == 1) ? -m0 : (pc0 == 3) ?  m0 : 0.f;
    float ar1 = (pc1 == 0) ?  m1 : (pc1 == 2) ? -m1 : 0.f;
    float ai1 = (pc1 == 1) ? -m1 : (pc1 == 3) ?  m1 : 0.f;

#pragma unroll
    for (int l = 0; l < 3; l++) {
        {   // RX on qubit0 (bit8): partner is own other amp.
            const float cq = wc[l * 4 + 0], sq = wsn[l * 4 + 0];
            float nr0 = fmaf(cq, ar0,  sq * ai1);
            float ni0 = fmaf(cq, ai0, -sq * ar1);
            float nr1 = fmaf(cq, ar1,  sq * ai0);
            float ni1 = fmaf(cq, ai1, -sq * ar0);
            ar0 = nr0; ai0 = ni0; ar1 = nr1; ai1 = ni1;
        }
#pragma unroll
        for (int q = 1; q < 4; q++) {  // bits 4,2,1 -> partner slot s^b
            const int b = 8 >> q;
            const float cq = wc[l * 4 + q], sq = wsn[l * 4 + q];
            float pr0 = SHFL8(ar0, b), pi0 = SHFL8(ai0, b);
            float pr1 = SHFL8(ar1, b), pi1 = SHFL8(ai1, b);
            float nr0 = fmaf(cq, ar0,  sq * pi0);
            float ni0 = fmaf(cq, ai0, -sq * pr0);
            float nr1 = fmaf(cq, ar1,  sq * pi1);
            float ni1 = fmaf(cq, ai1, -sq * pr1);
            ar0 = nr0; ai0 = ni0; ar1 = nr1; ai1 = ni1;
        }
        // CNOT(0,1): ctrl bit3, tgt bit4 — amp1 <- slot s^4's amp1.
        {
            float tr = SHFL8(ar1, 4), ti = SHFL8(ai1, 4);
            ar1 = tr; ai1 = ti;
        }
        // CNOT(1,2): ctrl bit2 (of s), tgt bit2.
        {
            float pr0 = SHFL8(ar0, 2), pi0 = SHFL8(ai0, 2);
            float pr1 = SHFL8(ar1, 2), pi1 = SHFL8(ai1, 2);
            const bool ct = (s >> 2) & 1;
            ar0 = ct ? pr0 : ar0;  ai0 = ct ? pi0 : ai0;
            ar1 = ct ? pr1 : ar1;  ai1 = ct ? pi1 : ai1;
        }
        // CNOT(2,3): ctrl bit1 (of s), tgt bit1.
        {
            float pr0 = SHFL8(ar0, 1), pi0 = SHFL8(ai0, 1);
            float pr1 = SHFL8(ar1, 1), pi1 = SHFL8(ai1, 1);
            const bool ct = (s >> 1) & 1;
            ar0 = ct ? pr0 : ar0;  ai0 = ct ? pi0 : ai0;
            ar1 = ct ? pr1 : ar1;  ai1 = ct ? pi1 : ai1;
        }
        // CNOT(3,0): ctrl bit0 (of s), tgt bit8 — in-thread amp swap.
        {
            const bool ct = s & 1;
            float tr = ar0, ti = ai0;
            ar0 = ct ? ar1 : ar0;  ai0 = ct ? ai1 : ai0;
            ar1 = ct ? tr  : ar1;  ai1 = ct ? ti  : ai1;
        }
    }

    // Probabilities + 4 signed (Walsh) sums reduced over the 8 slots.
    const float p0 = ar0 * ar0 + ai0 * ai0;
    const float p1 = ar1 * ar1 + ai1 * ai1;
    const float tsum = p0 + p1, tdiff = p0 - p1;
    float v0 = tdiff;
    float v1 = ((s >> 2) & 1) ? -tsum : tsum;
    float v2 = ((s >> 1) & 1) ? -tsum : tsum;
    float v3 = (s & 1)        ? -tsum : tsum;
#pragma unroll
    for (int d = 1; d < 8; d <<= 1) {
        v0 += SHFL8(v0, d);
        v1 += SHFL8(v1, d);
        v2 += SHFL8(v2, d);
        v3 += SHFL8(v3, d);
    }
    if (s == 0 && sm < 81) {
        bufA[0 * 81 + sm] = v0;
        bufA[1 * 81 + sm] = v1;
        bufA[2 * 81 + sm] = v2;
        bufA[3 * 81 + sm] = v3;
    }
    __syncthreads();

    // Inverse Vandermonde per axis (samples {0,pi/2,pi}, basis (1,cos,sin)):
    //   c0 = (s0+s2)/2 ; c1 = (s0-s2)/2 ; c2 = s1 - (s0+s2)/2
    const float Vi[3][3] = {{0.5f, 0.0f, 0.5f},
                            {0.5f, 0.0f, -0.5f},
                            {-0.5f, 1.0f, -0.5f}};
    const int WST[4] = {27, 9, 3, 1};
    float* src = bufA;
    float* dst = bufB;
    for (int ax = 3; ax >= 0; ax--) {
        if (t < 324) {
            const int o = t / 81, e = t % 81;
            const int ws2 = WST[ax];
            const int k = (e / ws2) % 3;
            const int eb = e - k * ws2;
            const float* sp = src + o * 81;
            dst[t] = Vi[k][0] * sp[eb] + Vi[k][1] * sp[eb + ws2] + Vi[k][2] * sp[eb + 2 * ws2];
        }
        __syncthreads();
        float* tmp = src; src = dst; dst = tmp;
    }

    if (t < 432) {
        const int o = t / 108, r = t % 108, k012 = r / 4, c = r % 4;
        g_T[t] = (c < 3) ? src[o * 81 + k012 * 3 + c] : 0.0f;
    }
}

// ---------------------------------------------------------------------------
// Kernel 2: ONE element per thread (no loop), PDL-gated T read.
// 320 FMA/element Horner over T.
// ---------------------------------------------------------------------------
__global__ __launch_bounds__(256, 4) void qlayer_kernel(
    const float* __restrict__ x, float* __restrict__ out, int B)
{
    __shared__ __align__(16) float4 shT[108];   // [o*27 + k0*9 + k1*3 + k2], .xyz = k3
    const int t = threadIdx.x;
    const int e = blockIdx.x * 256 + t;
    const bool active = (e < B);

    // Prolog (independent of T): overlaps with build_T under PDL.
    float c0, s0, c1, s1, c2, s2, c3, s3;
    if (active) {
        const float4 v = ((const float4*)x)[e];
        __sincosf(v.x, &s0, &c0);
        __sincosf(v.y, &s1, &c1);
        __sincosf(v.z, &s2, &c2);
        __sincosf(v.w, &s3, &c3);
    }

    // Gate: wait for build_T completion + memory visibility.
    cudaGridDependencySynchronize();

    if (t < 108) shT[t] = __ldcg(((const float4*)g_T) + t);
    __syncthreads();

    if (active) {
        float o0, o1, o2, o3;
#pragma unroll
        for (int o = 0; o < 4; o++) {
            float acc;
#pragma unroll
            for (int k0 = 0; k0 < 3; k0++) {
                float Aacc;
#pragma unroll
                for (int k1 = 0; k1 < 3; k1++) {
                    float Bacc;
#pragma unroll
                    for (int k2 = 0; k2 < 3; k2++) {
                        const float4 tq = shT[o * 27 + k0 * 9 + k1 * 3 + k2];
                        const float D = fmaf(tq.z, s3, fmaf(tq.y, c3, tq.x));
                        if (k2 == 0)      Bacc = D;
                        else if (k2 == 1) Bacc = fmaf(c2, D, Bacc);
                        else              Bacc = fmaf(s2, D, Bacc);
                    }
                    if (k1 == 0)      Aacc = Bacc;
                    else if (k1 == 1) Aacc = fmaf(c1, Bacc, Aacc);
                    else              Aacc = fmaf(s1, Bacc, Aacc);
                }
                if (k0 == 0)      acc = Aacc;
                else if (k0 == 1) acc = fmaf(c0, Aacc, acc);
                else              acc = fmaf(s0, Aacc, acc);
            }
            if (o == 0)      o0 = acc;
            else if (o == 1) o1 = acc;
            else if (o == 2) o2 = acc;
            else             o3 = acc;
        }

        ((float4*)out)[e] = make_float4(o0, o1, o2, o3);
    }
}

// ---------------------------------------------------------------------------
extern "C" void kernel_launch(void* const* d_in, const int* in_sizes, int n_in,
                              void* d_out, int out_size) {
    const float* xp = (const float*)d_in[0];
    const float* wp = (const float*)d_in[1];
    int sx = in_sizes[0];
    if (n_in >= 2 && in_sizes[0] == 12 && in_sizes[1] != 12) {
        xp = (const float*)d_in[1];
        wp = (const float*)d_in[0];
        sx = in_sizes[1];
    }
    const int B = sx / 4;

    build_T_kernel<<<1, 672>>>(wp);

    const int grid = (B + 255) / 256;   // E=1: 4096 blocks for B=2^20

    // PDL: secondary may launch as soon as build_T triggers (at its start);
    // the in-kernel cudaGridDependencySynchronize() gates the T read.
    cudaLaunchConfig_t cfg = {};
    cfg.gridDim = dim3((unsigned)grid);
    cfg.blockDim = dim3(256);
    cfg.dynamicSmemBytes = 0;
    cfg.stream = 0;
    cudaLaunchAttribute attr[1];
    attr[0].id = cudaLaunchAttributeProgrammaticStreamSerialization;
    attr[0].val.programmaticStreamSerializationAllowed = 1;
    cfg.attrs = attr;
    cfg.numAttrs = 1;
    cudaError_t err = cudaLaunchKernelEx(&cfg, qlayer_kernel, xp, (float*)d_out, B);
    if (err != cudaSuccess) {
        qlayer_kernel<<<grid, 256>>>(xp, (float*)d_out, B);
    }
}

// round 17
// speedup vs baseline: 7.1745x; 2.0660x over previous
#include <cuda_runtime.h>
#include <cuda_bf16.h>
#include <math.h>

// QuantumLayer as a multilinear polynomial (exact identity):
//   out_o(x) = T[o] . (1,cos x0,sin x0) x ... x (1,cos x3,sin x3)
// T (4 x 3^4) built by sampling the circuit at {0,pi/2,pi}^4 + inverse 3x3
// Vandermonde. Two kernels under PDL (champion structure).
// R17: MIXED-E hot grid: 2368 blocks = exactly 4 waves of 592 slots.
// Blocks [0,1728): E=2 straight-line (512 elems) — the proven champion body.
// Blocks [1728,2368): E=1 straight-line (256 elems).
// Per-slot packing {2,2,2,1}/{2,2,1,1} units -> makespan 7 vs mean 6.92 =
// 1.2% idle, vs 13.5% at uniform E=2 (3.46 waves, makespan 4).
// Constraints honored: no per-thread loop (ptxas local-mem demotion law,
// R11/12/15), E>=2 for most blocks (T-load amortization, R16).

__device__ __align__(16) float g_T[432];  // [o][k0][k1][k2][k3 padded to 4]

#define SHFL8(v, m) __shfl_xor_sync(0xFFFFFFFFu, (v), (m), 8)

// ---------------------------------------------------------------------------
// Kernel 1: build T. One block, 672 threads = 21 warps x 4 samples x 8 lanes.
// ---------------------------------------------------------------------------
__global__ void build_T_kernel(const float* __restrict__ w) {
    // Let the PDL secondary launch immediately; everything it does before
    // cudaGridDependencySynchronize() is T-independent.
    cudaTriggerProgrammaticLaunchCompletion();

    __shared__ float bufA[324], bufB[324];
    __shared__ float wc[12], wsn[12];
    const int t = threadIdx.x;

    if (t < 12) {
        float s, c;
        __sincosf(0.5f * w[t], &s, &c);
        wc[t] = c; wsn[t] = s;
    }
    __syncthreads();

    const int lane = t & 31;
    const int s    = lane & 7;                    // slot: owns amps s and s+8
    const int sm   = (t >> 5) * 4 + (lane >> 3);  // sample id (0..83; >=81 unused)

    const int a0 = sm / 27, a1 = (sm / 9) % 3, a2 = (sm / 3) % 3, a3 = sm % 3;
    const float R = 0.70710678118654752f;
    const float hc0 = (a0 == 0) ? 1.f : (a0 == 1) ? R : 0.f;
    const float hs0 = (a0 == 0) ? 0.f : (a0 == 1) ? R : 1.f;
    const float hc1 = (a1 == 0) ? 1.f : (a1 == 1) ? R : 0.f;
    const float hs1 = (a1 == 0) ? 0.f : (a1 == 1) ? R : 1.f;
    const float hc2 = (a2 == 0) ? 1.f : (a2 == 1) ? R : 0.f;
    const float hs2 = (a2 == 0) ? 0.f : (a2 == 1) ? R : 1.f;
    const float hc3 = (a3 == 0) ? 1.f : (a3 == 1) ? R : 0.f;
    const float hs3 = (a3 == 0) ? 0.f : (a3 == 1) ? R : 1.f;

    // Post-input-RX product state: amp_j = (-i)^popc(j) * prod_q f_q(bit(3-q))
    const float f1 = ((s >> 2) & 1) ? hs1 : hc1;
    const float f2 = ((s >> 1) & 1) ? hs2 : hc2;
    const float f3 = (s & 1)        ? hs3 : hc3;
    const float rest = f1 * f2 * f3;
    const float m0 = hc0 * rest;   // amp j=s   (bit3=0)
    const float m1 = hs0 * rest;   // amp j=s+8 (bit3=1)

    const int pc0 = __popc(s) & 3;
    const int pc1 = (pc0 + 1) & 3;
    float ar0 = (pc0 == 0) ?  m0 : (pc0 == 2) ? -m0 : 0.f;
    float ai0 = (pc0 == 1) ? -m0 : (pc0 == 3) ?  m0 : 0.f;
    float ar1 = (pc1 == 0) ?  m1 : (pc1 == 2) ? -m1 : 0.f;
    float ai1 = (pc1 == 1) ? -m1 : (pc1 == 3) ?  m1 : 0.f;

#pragma unroll
    for (int l = 0; l < 3; l++) {
        {   // RX on qubit0 (bit8): partner is own other amp.
            const float cq = wc[l * 4 + 0], sq = wsn[l * 4 + 0];
            float nr0 = fmaf(cq, ar0,  sq * ai1);
            float ni0 = fmaf(cq, ai0, -sq * ar1);
            float nr1 = fmaf(cq, ar1,  sq * ai0);
            float ni1 = fmaf(cq, ai1, -sq * ar0);
            ar0 = nr0; ai0 = ni0; ar1 = nr1; ai1 = ni1;
        }
#pragma unroll
        for (int q = 1; q < 4; q++) {  // bits 4,2,1 -> partner slot s^b
            const int b = 8 >> q;
            const float cq = wc[l * 4 + q], sq = wsn[l * 4 + q];
            float pr0 = SHFL8(ar0, b), pi0 = SHFL8(ai0, b);
            float pr1 = SHFL8(ar1, b), pi1 = SHFL8(ai1, b);
            float nr0 = fmaf(cq, ar0,  sq * pi0);
            float ni0 = fmaf(cq, ai0, -sq * pr0);
            float nr1 = fmaf(cq, ar1,  sq * pi1);
            float ni1 = fmaf(cq, ai1, -sq * pr1);
            ar0 = nr0; ai0 = ni0; ar1 = nr1; ai1 = ni1;
        }
        // CNOT(0,1): ctrl bit3, tgt bit4 — amp1 <- slot s^4's amp1.
        {
            float tr = SHFL8(ar1, 4), ti = SHFL8(ai1, 4);
            ar1 = tr; ai1 = ti;
        }
        // CNOT(1,2): ctrl bit2 (of s), tgt bit2.
        {
            float pr0 = SHFL8(ar0, 2), pi0 = SHFL8(ai0, 2);
            float pr1 = SHFL8(ar1, 2), pi1 = SHFL8(ai1, 2);
            const bool ct = (s >> 2) & 1;
            ar0 = ct ? pr0 : ar0;  ai0 = ct ? pi0 : ai0;
            ar1 = ct ? pr1 : ar1;  ai1 = ct ? pi1 : ai1;
        }
        // CNOT(2,3): ctrl bit1 (of s), tgt bit1.
        {
            float pr0 = SHFL8(ar0, 1), pi0 = SHFL8(ai0, 1);
            float pr1 = SHFL8(ar1, 1), pi1 = SHFL8(ai1, 1);
            const bool ct = (s >> 1) & 1;
            ar0 = ct ? pr0 : ar0;  ai0 = ct ? pi0 : ai0;
            ar1 = ct ? pr1 : ar1;  ai1 = ct ? pi1 : ai1;
        }
        // CNOT(3,0): ctrl bit0 (of s), tgt bit8 — in-thread amp swap.
        {
            const bool ct = s & 1;
            float tr = ar0, ti = ai0;
            ar0 = ct ? ar1 : ar0;  ai0 = ct ? ai1 : ai0;
            ar1 = ct ? tr  : ar1;  ai1 = ct ? ti  : ai1;
        }
    }

    // Probabilities + 4 signed (Walsh) sums reduced over the 8 slots.
    const float p0 = ar0 * ar0 + ai0 * ai0;
    const float p1 = ar1 * ar1 + ai1 * ai1;
    const float tsum = p0 + p1, tdiff = p0 - p1;
    float v0 = tdiff;
    float v1 = ((s >> 2) & 1) ? -tsum : tsum;
    float v2 = ((s >> 1) & 1) ? -tsum : tsum;
    float v3 = (s & 1)        ? -tsum : tsum;
#pragma unroll
    for (int d = 1; d < 8; d <<= 1) {
        v0 += SHFL8(v0, d);
        v1 += SHFL8(v1, d);
        v2 += SHFL8(v2, d);
        v3 += SHFL8(v3, d);
    }
    if (s == 0 && sm < 81) {
        bufA[0 * 81 + sm] = v0;
        bufA[1 * 81 + sm] = v1;
        bufA[2 * 81 + sm] = v2;
        bufA[3 * 81 + sm] = v3;
    }
    __syncthreads();

    // Inverse Vandermonde per axis (samples {0,pi/2,pi}, basis (1,cos,sin)):
    //   c0 = (s0+s2)/2 ; c1 = (s0-s2)/2 ; c2 = s1 - (s0+s2)/2
    const float Vi[3][3] = {{0.5f, 0.0f, 0.5f},
                            {0.5f, 0.0f, -0.5f},
                            {-0.5f, 1.0f, -0.5f}};
    const int WST[4] = {27, 9, 3, 1};
    float* src = bufA;
    float* dst = bufB;
    for (int ax = 3; ax >= 0; ax--) {
        if (t < 324) {
            const int o = t / 81, e = t % 81;
            const int ws2 = WST[ax];
            const int k = (e / ws2) % 3;
            const int eb = e - k * ws2;
            const float* sp = src + o * 81;
            dst[t] = Vi[k][0] * sp[eb] + Vi[k][1] * sp[eb + ws2] + Vi[k][2] * sp[eb + 2 * ws2];
        }
        __syncthreads();
        float* tmp = src; src = dst; dst = tmp;
    }

    if (t < 432) {
        const int o = t / 108, r = t % 108, k012 = r / 4, c = r % 4;
        g_T[t] = (c < 3) ? src[o * 81 + k012 * 3 + c] : 0.0f;
    }
}

// ---------------------------------------------------------------------------
// The 320-FMA Horner for one element (given its 8 sincos values).
// ---------------------------------------------------------------------------
__device__ __forceinline__ float4 horner1(
    const float4* __restrict__ shT,
    float c0, float s0, float c1, float s1,
    float c2, float s2, float c3, float s3)
{
    float oo[4];
#pragma unroll
    for (int o = 0; o < 4; o++) {
        float acc;
#pragma unroll
        for (int k0 = 0; k0 < 3; k0++) {
            float Aacc;
#pragma unroll
            for (int k1 = 0; k1 < 3; k1++) {
                float Bacc;
#pragma unroll
                for (int k2 = 0; k2 < 3; k2++) {
                    const float4 tq = shT[o * 27 + k0 * 9 + k1 * 3 + k2];
                    const float D = fmaf(tq.z, s3, fmaf(tq.y, c3, tq.x));
                    if (k2 == 0)      Bacc = D;
                    else if (k2 == 1) Bacc = fmaf(c2, D, Bacc);
                    else              Bacc = fmaf(s2, D, Bacc);
                }
                if (k1 == 0)      Aacc = Bacc;
                else if (k1 == 1) Aacc = fmaf(c1, Bacc, Aacc);
                else              Aacc = fmaf(s1, Bacc, Aacc);
            }
            if (k0 == 0)      acc = Aacc;
            else if (k0 == 1) acc = fmaf(c0, Aacc, acc);
            else              acc = fmaf(s0, Aacc, acc);
        }
        oo[o] = acc;
    }
    return make_float4(oo[0], oo[1], oo[2], oo[3]);
}

// ---------------------------------------------------------------------------
// Kernel 2: mixed-E. Blocks [0,N2): E=2 (512 elems); blocks [N2,G): E=1.
// ---------------------------------------------------------------------------
__global__ __launch_bounds__(256, 4) void qlayer_kernel(
    const float* __restrict__ x, float* __restrict__ out, int B, int N2)
{
    __shared__ __align__(16) float4 shT[108];   // [o*27 + k0*9 + k1*3 + k2]
    const int t = threadIdx.x;
    const bool isE2 = ((int)blockIdx.x < N2);

    // Element indices.
    const int e0 = isE2 ? (blockIdx.x * 512 + t * 2)
                        : (N2 * 512 + ((int)blockIdx.x - N2) * 256 + t);
    const bool a0v = (e0 < B);
    const bool a1v = isE2 && (e0 + 1 < B);

    // Prolog (independent of T): overlaps with build_T under PDL.
    const float4* __restrict__ x4 = (const float4*)x;
    float c0a, s0a, c1a, s1a, c2a, s2a, c3a, s3a;
    float c0b, s0b, c1b, s1b, c2b, s2b, c3b, s3b;
    if (a0v) {
        const float4 v = x4[e0];
        __sincosf(v.x, &s0a, &c0a);
        __sincosf(v.y, &s1a, &c1a);
        __sincosf(v.z, &s2a, &c2a);
        __sincosf(v.w, &s3a, &c3a);
    }
    if (a1v) {
        const float4 v = x4[e0 + 1];
        __sincosf(v.x, &s0b, &c0b);
        __sincosf(v.y, &s1b, &c1b);
        __sincosf(v.z, &s2b, &c2b);
        __sincosf(v.w, &s3b, &c3b);
    }

    // Gate: wait for build_T completion + memory visibility.
    cudaGridDependencySynchronize();

    if (t < 108) shT[t] = __ldcg(((const float4*)g_T) + t);
    __syncthreads();

    float4* __restrict__ o4 = (float4*)out;
    if (isE2) {
        if (a0v) {
            // Two elements, interleaved by the compiler over shared tq loads.
            float oo[2][4];
#pragma unroll
            for (int o = 0; o < 4; o++) {
                float acc[2];
#pragma unroll
                for (int k0 = 0; k0 < 3; k0++) {
                    float Aacc[2];
#pragma unroll
                    for (int k1 = 0; k1 < 3; k1++) {
                        float Bacc[2];
#pragma unroll
                        for (int k2 = 0; k2 < 3; k2++) {
                            const float4 tq = shT[o * 27 + k0 * 9 + k1 * 3 + k2];
                            const float Da = fmaf(tq.z, s3a, fmaf(tq.y, c3a, tq.x));
                            const float Db = fmaf(tq.z, s3b, fmaf(tq.y, c3b, tq.x));
                            if (k2 == 0)      { Bacc[0] = Da; Bacc[1] = Db; }
                            else if (k2 == 1) { Bacc[0] = fmaf(c2a, Da, Bacc[0]); Bacc[1] = fmaf(c2b, Db, Bacc[1]); }
                            else              { Bacc[0] = fmaf(s2a, Da, Bacc[0]); Bacc[1] = fmaf(s2b, Db, Bacc[1]); }
                        }
                        if (k1 == 0)      { Aacc[0] = Bacc[0]; Aacc[1] = Bacc[1]; }
                        else if (k1 == 1) { Aacc[0] = fmaf(c1a, Bacc[0], Aacc[0]); Aacc[1] = fmaf(c1b, Bacc[1], Aacc[1]); }
                        else              { Aacc[0] = fmaf(s1a, Bacc[0], Aacc[0]); Aacc[1] = fmaf(s1b, Bacc[1], Aacc[1]); }
                    }
                    if (k0 == 0)      { acc[0] = Aacc[0]; acc[1] = Aacc[1]; }
                    else if (k0 == 1) { acc[0] = fmaf(c0a, Aacc[0], acc[0]); acc[1] = fmaf(c0b, Aacc[1], acc[1]); }
                    else              { acc[0] = fmaf(s0a, Aacc[0], acc[0]); acc[1] = fmaf(s0b, Aacc[1], acc[1]); }
                }
                oo[0][o] = acc[0]; oo[1][o] = acc[1];
            }
            o4[e0] = make_float4(oo[0][0], oo[0][1], oo[0][2], oo[0][3]);
            if (a1v) o4[e0 + 1] = make_float4(oo[1][0], oo[1][1], oo[1][2], oo[1][3]);
        }
    } else {
        if (a0v) {
            o4[e0] = horner1(shT, c0a, s0a, c1a, s1a, c2a, s2a, c3a, s3a);
        }
    }
}

// ---------------------------------------------------------------------------
extern "C" void kernel_launch(void* const* d_in, const int* in_sizes, int n_in,
                              void* d_out, int out_size) {
    const float* xp = (const float*)d_in[0];
    const float* wp = (const float*)d_in[1];
    int sx = in_sizes[0];
    if (n_in >= 2 && in_sizes[0] == 12 && in_sizes[1] != 12) {
        xp = (const float*)d_in[1];
        wp = (const float*)d_in[0];
        sx = in_sizes[1];
    }
    const int B = sx / 4;

    build_T_kernel<<<1, 672>>>(wp);

    // Mixed-E grid: units = 256-element columns. Target G = 2368 (4 waves of
    // 592 slots). N2 E=2 blocks + (G-N2) E=1 blocks with N2*2 + (G-N2) = units.
    const int units = (B + 255) / 256;
    int G, N2;
    if (units > 2368 && (units - 2368) <= 2368) {
        G = 2368;
        N2 = units - G;           // e.g. 4096 units -> N2=1728, 640 E=1 blocks
    } else if (units <= 2368) {
        G = units; N2 = 0;        // small B: all E=1
    } else {
        G = (units + 1) / 2; N2 = G;  // huge B: all E=2
    }

    // PDL: secondary may launch as soon as build_T triggers (at its start);
    // the in-kernel cudaGridDependencySynchronize() gates the T read.
    cudaLaunchConfig_t cfg = {};
    cfg.gridDim = dim3((unsigned)G);
    cfg.blockDim = dim3(256);
    cfg.dynamicSmemBytes = 0;
    cfg.stream = 0;
    cudaLaunchAttribute attr[1];
    attr[0].id = cudaLaunchAttributeProgrammaticStreamSerialization;
    attr[0].val.programmaticStreamSerializationAllowed = 1;
    cfg.attrs = attr;
    cfg.numAttrs = 1;
    cudaError_t err = cudaLaunchKernelEx(&cfg, qlayer_kernel, xp, (float*)d_out, B, N2);
    if (err != cudaSuccess) {
        qlayer_kernel<<<G, 256>>>(xp, (float*)d_out, B, N2);
    }
}